// round 1
// baseline (speedup 1.0000x reference)
#include <cuda_runtime.h>
#include <math.h>

// Problem dims
#define BZ 4
#define TZ 2048
#define CZ 1024
#define HZ 16
#define HDZ 64
// scale = 1/sqrt(B) (faithful to reference)
#define ATT_SCALE 0.5f

// Scratch (device globals; no allocation allowed)
__device__ float g_qp[(size_t)BZ * HZ * TZ * HDZ];   // [B,H,T,HD]
__device__ float g_kp[(size_t)BZ * HZ * TZ * HDZ];
__device__ float g_vp[(size_t)BZ * HZ * TZ * HDZ];
__device__ float g_att[(size_t)BZ * TZ * CZ];        // [B,T,C] (head-interleaved)

// ---------------------------------------------------------------------------
// Tiled fp32 GEMM: Y = X @ W^T (+bias), X:[M,K], W:[N,K]
// BM=BN=64, BK=16, 256 threads, 4x4 per-thread register tile.
// HEAD_LAYOUT: write Y as [B,H,T,HD] (n-tile of 64 == one head)
// else: plain [M,N] row-major (+ optional bias).
// ---------------------------------------------------------------------------
template<bool HEAD_LAYOUT, bool BIAS>
__global__ __launch_bounds__(256)
void gemm64_kernel(const float* __restrict__ X, const float* __restrict__ W,
                   const float* __restrict__ bias, float* __restrict__ Y)
{
    const int K = CZ;
    __shared__ float As[16][64];  // As[k][m]
    __shared__ float Bs[16][64];  // Bs[k][n]

    const int tid = threadIdx.x;
    const int tx = tid & 15;       // n quad
    const int ty = tid >> 4;       // m quad
    const int m0 = blockIdx.y * 64;
    const int n0 = blockIdx.x * 64;

    const int lrow = tid >> 2;           // 0..63
    const int lk4  = (tid & 3) * 4;      // 0,4,8,12

    const float* Xp = X + (size_t)(m0 + lrow) * K;
    const float* Wp = W + (size_t)(n0 + lrow) * K;

    float acc[4][4];
#pragma unroll
    for (int i = 0; i < 4; i++)
#pragma unroll
        for (int j = 0; j < 4; j++) acc[i][j] = 0.f;

    for (int k0 = 0; k0 < K; k0 += 16) {
        float4 a = *(const float4*)(Xp + k0 + lk4);
        float4 b = *(const float4*)(Wp + k0 + lk4);
        As[lk4 + 0][lrow] = a.x; As[lk4 + 1][lrow] = a.y;
        As[lk4 + 2][lrow] = a.z; As[lk4 + 3][lrow] = a.w;
        Bs[lk4 + 0][lrow] = b.x; Bs[lk4 + 1][lrow] = b.y;
        Bs[lk4 + 2][lrow] = b.z; Bs[lk4 + 3][lrow] = b.w;
        __syncthreads();
#pragma unroll
        for (int k = 0; k < 16; k++) {
            float4 av = *(const float4*)&As[k][ty * 4];
            float4 bv = *(const float4*)&Bs[k][tx * 4];
            float am[4] = {av.x, av.y, av.z, av.w};
            float bn[4] = {bv.x, bv.y, bv.z, bv.w};
#pragma unroll
            for (int i = 0; i < 4; i++)
#pragma unroll
                for (int j = 0; j < 4; j++) acc[i][j] += am[i] * bn[j];
        }
        __syncthreads();
    }

    if (HEAD_LAYOUT) {
        const int b = m0 / TZ;
        const int h = n0 / HDZ;
#pragma unroll
        for (int i = 0; i < 4; i++) {
            const int t = (m0 % TZ) + ty * 4 + i;
            float* yp = Y + (((size_t)b * HZ + h) * TZ + t) * HDZ + tx * 4;
            float4 o = make_float4(acc[i][0], acc[i][1], acc[i][2], acc[i][3]);
            *(float4*)yp = o;
        }
    } else {
#pragma unroll
        for (int i = 0; i < 4; i++) {
            const int m = m0 + ty * 4 + i;
            float* yp = Y + (size_t)m * CZ + n0 + tx * 4;
            float4 o = make_float4(acc[i][0], acc[i][1], acc[i][2], acc[i][3]);
            if (BIAS) {
                const float* bp = bias + n0 + tx * 4;
                o.x += bp[0]; o.y += bp[1]; o.z += bp[2]; o.w += bp[3];
            }
            *(float4*)yp = o;
        }
    }
}

// ---------------------------------------------------------------------------
// Flash attention (causal), fp32. One CTA = one (b*h, 64-row Q tile).
// Streams 64-row KV tiles; only diagonal tile needs masking; tiles past the
// diagonal are skipped. smem stride 72 to dodge bank conflicts.
// ---------------------------------------------------------------------------
#define LDS 72
#define FLASH_SMEM ((4 * 64 * LDS + 3 * 64) * sizeof(float))

__global__ __launch_bounds__(256)
void flash_attn_kernel(float* __restrict__ ATT)
{
    extern __shared__ float sm[];
    float* Qt  = sm;                 // Qt[d][r]  (d-major)
    float* Kt  = Qt + 64 * LDS;      // Kt[d][c]
    float* Vs  = Kt + 64 * LDS;      // Vs[c][d]
    float* St  = Vs + 64 * LDS;      // St[c][r]  (S / P transposed)
    float* m_s = St + 64 * LDS;      // [64]
    float* l_s = m_s + 64;
    float* al_s = l_s + 64;

    const int tid = threadIdx.x;
    const int tx = tid & 15, ty = tid >> 4;
    const int qt = blockIdx.x;          // q tile (0..31)
    const int bh = blockIdx.y;          // 0..63
    const int q0 = qt * 64;

    const int lrow = tid >> 2;          // 0..63
    const int dseg = (tid & 3) * 16;    // 16 d's per thread

    const float* Qg = g_qp + ((size_t)bh * TZ + q0) * HDZ;

    // Load Q transposed: Qt[d][r]
#pragma unroll
    for (int u = 0; u < 4; u++) {
        float4 a = *(const float4*)(Qg + (size_t)lrow * HDZ + dseg + u * 4);
        Qt[(dseg + u * 4 + 0) * LDS + lrow] = a.x;
        Qt[(dseg + u * 4 + 1) * LDS + lrow] = a.y;
        Qt[(dseg + u * 4 + 2) * LDS + lrow] = a.z;
        Qt[(dseg + u * 4 + 3) * LDS + lrow] = a.w;
    }
    if (tid < 64) { m_s[tid] = -INFINITY; l_s[tid] = 0.f; }

    float o[4][4];
#pragma unroll
    for (int i = 0; i < 4; i++)
#pragma unroll
        for (int j = 0; j < 4; j++) o[i][j] = 0.f;

    for (int jt = 0; jt <= qt; jt++) {
        const int k0 = jt * 64;
        const float* Kg = g_kp + ((size_t)bh * TZ + k0) * HDZ;
        const float* Vg = g_vp + ((size_t)bh * TZ + k0) * HDZ;
        __syncthreads();   // protect Kt/Vs/St from previous iteration's readers
#pragma unroll
        for (int u = 0; u < 4; u++) {
            float4 kv = *(const float4*)(Kg + (size_t)lrow * HDZ + dseg + u * 4);
            Kt[(dseg + u * 4 + 0) * LDS + lrow] = kv.x;
            Kt[(dseg + u * 4 + 1) * LDS + lrow] = kv.y;
            Kt[(dseg + u * 4 + 2) * LDS + lrow] = kv.z;
            Kt[(dseg + u * 4 + 3) * LDS + lrow] = kv.w;
            float4 vv = *(const float4*)(Vg + (size_t)lrow * HDZ + dseg + u * 4);
            *(float4*)&Vs[lrow * LDS + dseg + u * 4] = vv;
        }
        __syncthreads();

        // S = Q K^T * scale (4x4 per thread), write transposed into St[c][r]
        float s[4][4];
#pragma unroll
        for (int i = 0; i < 4; i++)
#pragma unroll
            for (int j = 0; j < 4; j++) s[i][j] = 0.f;
#pragma unroll
        for (int d = 0; d < 64; d++) {
            float4 av = *(const float4*)&Qt[d * LDS + ty * 4];
            float4 bv = *(const float4*)&Kt[d * LDS + tx * 4];
            float am[4] = {av.x, av.y, av.z, av.w};
            float bn[4] = {bv.x, bv.y, bv.z, bv.w};
#pragma unroll
            for (int i = 0; i < 4; i++)
#pragma unroll
                for (int j = 0; j < 4; j++) s[i][j] += am[i] * bn[j];
        }
        const bool diag = (jt == qt);
#pragma unroll
        for (int i = 0; i < 4; i++) {
            const int qi = ty * 4 + i;             // row within tile (q0 offset equal for k)
#pragma unroll
            for (int j = 0; j < 4; j++) {
                float val = s[i][j] * ATT_SCALE;
                if (diag && (tx * 4 + j) > qi) val = -1e30f;
                St[(tx * 4 + j) * LDS + ty * 4 + i] = val;
            }
        }
        __syncthreads();

        // Online softmax: 4 threads per row, 16 cols each
        {
            const int r = tid >> 2;
            const int cbase = (tid & 3) * 16;
            float mx = -1e30f;
#pragma unroll
            for (int c = 0; c < 16; c++)
                mx = fmaxf(mx, St[(cbase + c) * LDS + r]);
            mx = fmaxf(mx, __shfl_xor_sync(0xffffffff, mx, 1));
            mx = fmaxf(mx, __shfl_xor_sync(0xffffffff, mx, 2));
            const float m_old = m_s[r];
            const float m_new = fmaxf(m_old, mx);
            float sum = 0.f;
#pragma unroll
            for (int c = 0; c < 16; c++) {
                float p = __expf(St[(cbase + c) * LDS + r] - m_new);
                St[(cbase + c) * LDS + r] = p;
                sum += p;
            }
            sum += __shfl_xor_sync(0xffffffff, sum, 1);
            sum += __shfl_xor_sync(0xffffffff, sum, 2);
            if ((tid & 3) == 0) {
                const float al = __expf(m_old - m_new);
                al_s[r] = al;
                l_s[r] = l_s[r] * al + sum;
                m_s[r] = m_new;
            }
        }
        __syncthreads();

        // O = O*alpha + P @ V
        float alr[4];
#pragma unroll
        for (int i = 0; i < 4; i++) alr[i] = al_s[ty * 4 + i];
#pragma unroll
        for (int i = 0; i < 4; i++)
#pragma unroll
            for (int j = 0; j < 4; j++) o[i][j] *= alr[i];
#pragma unroll
        for (int c = 0; c < 64; c++) {
            float4 pv = *(const float4*)&St[c * LDS + ty * 4];
            float4 vv = *(const float4*)&Vs[c * LDS + tx * 4];
            float pm[4] = {pv.x, pv.y, pv.z, pv.w};
            float vn[4] = {vv.x, vv.y, vv.z, vv.w};
#pragma unroll
            for (int i = 0; i < 4; i++)
#pragma unroll
                for (int j = 0; j < 4; j++) o[i][j] += pm[i] * vn[j];
        }
    }
    __syncthreads();

    // Normalize and write to [B,T,C] with head interleave
    const int b = bh / HZ;
    const int h = bh % HZ;
#pragma unroll
    for (int i = 0; i < 4; i++) {
        const float inv = 1.f / l_s[ty * 4 + i];
        const int t = q0 + ty * 4 + i;
        float* yp = ATT + ((size_t)(b * TZ + t)) * CZ + h * HDZ + tx * 4;
        float4 ov = make_float4(o[i][0] * inv, o[i][1] * inv, o[i][2] * inv, o[i][3] * inv);
        *(float4*)yp = ov;
    }
}

// ---------------------------------------------------------------------------
extern "C" void kernel_launch(void* const* d_in, const int* in_sizes, int n_in,
                              void* d_out, int out_size)
{
    const float* v  = (const float*)d_in[0];
    const float* k  = (const float*)d_in[1];
    const float* q  = (const float*)d_in[2];
    // d_in[3] = mask (exact causal tril; handled analytically)
    const float* Wk = (const float*)d_in[4];
    const float* Wq = (const float*)d_in[5];
    const float* Wv = (const float*)d_in[6];
    const float* Wo = (const float*)d_in[7];
    const float* bo = (const float*)d_in[8];
    float* out = (float*)d_out;

    float *qp, *kp, *vp, *att;
    cudaGetSymbolAddress((void**)&qp, g_qp);
    cudaGetSymbolAddress((void**)&kp, g_kp);
    cudaGetSymbolAddress((void**)&vp, g_vp);
    cudaGetSymbolAddress((void**)&att, g_att);

    cudaFuncSetAttribute(flash_attn_kernel,
                         cudaFuncAttributeMaxDynamicSharedMemorySize, FLASH_SMEM);

    dim3 gg(CZ / 64, (BZ * TZ) / 64);   // (16, 128)
    gemm64_kernel<true, false><<<gg, 256>>>(q, Wq, nullptr, qp);
    gemm64_kernel<true, false><<<gg, 256>>>(k, Wk, nullptr, kp);
    gemm64_kernel<true, false><<<gg, 256>>>(v, Wv, nullptr, vp);

    dim3 fg(TZ / 64, BZ * HZ);          // (32, 64)
    flash_attn_kernel<<<fg, 256, FLASH_SMEM>>>(att);

    gemm64_kernel<false, true><<<gg, 256>>>(att, Wo, bo, out);
}

// round 10
// speedup vs baseline: 1.5027x; 1.5027x over previous
#include <cuda_runtime.h>
#include <cuda_bf16.h>
#include <math.h>
#include <stdint.h>

// Problem dims
#define BZ 4
#define TZ 2048
#define CZ 1024
#define HZ 16
#define HDZ 64
#define ATT_SCALE 0.5f   // 1/sqrt(B), faithful to reference

// ---------------------------------------------------------------------------
// Scratch (device globals; no allocation allowed)
// ---------------------------------------------------------------------------
__device__ float g_qp[(size_t)BZ * HZ * TZ * HDZ];   // [B,H,T,HD]
__device__ float g_kp[(size_t)BZ * HZ * TZ * HDZ];
__device__ float g_vp[(size_t)BZ * HZ * TZ * HDZ];
__device__ float g_att[(size_t)BZ * TZ * CZ];        // [B,T,C]
__device__ __nv_bfloat16 g_xh[(size_t)BZ * TZ * CZ]; // split-bf16 X (hi/lo)
__device__ __nv_bfloat16 g_xl[(size_t)BZ * TZ * CZ];
__device__ __nv_bfloat16 g_wh[(size_t)CZ * CZ];      // split-bf16 W (hi/lo)
__device__ __nv_bfloat16 g_wl[(size_t)CZ * CZ];

// ---------------------------------------------------------------------------
// fp32 -> (hi, lo) bf16 split
// ---------------------------------------------------------------------------
__global__ __launch_bounds__(256)
void split_kernel(const float* __restrict__ x, __nv_bfloat16* __restrict__ hi,
                  __nv_bfloat16* __restrict__ lo, int n)
{
    int i = (blockIdx.x * 256 + threadIdx.x) * 4;
    if (i >= n) return;
    float4 v = *(const float4*)(x + i);
    __nv_bfloat16 h0 = __float2bfloat16(v.x), h1 = __float2bfloat16(v.y);
    __nv_bfloat16 h2 = __float2bfloat16(v.z), h3 = __float2bfloat16(v.w);
    __nv_bfloat16 l0 = __float2bfloat16(v.x - __bfloat162float(h0));
    __nv_bfloat16 l1 = __float2bfloat16(v.y - __bfloat162float(h1));
    __nv_bfloat16 l2 = __float2bfloat16(v.z - __bfloat162float(h2));
    __nv_bfloat16 l3 = __float2bfloat16(v.w - __bfloat162float(h3));
    ushort4 ho, lov;
    ho.x = *(unsigned short*)&h0; ho.y = *(unsigned short*)&h1;
    ho.z = *(unsigned short*)&h2; ho.w = *(unsigned short*)&h3;
    lov.x = *(unsigned short*)&l0; lov.y = *(unsigned short*)&l1;
    lov.z = *(unsigned short*)&l2; lov.w = *(unsigned short*)&l3;
    *(ushort4*)(hi + i) = ho;
    *(ushort4*)(lo + i) = lov;
}

// ---------------------------------------------------------------------------
// mma.sync m16n8k16 bf16 (fp32 accum) — standard PTX, valid on compute_103
// ---------------------------------------------------------------------------
__device__ __forceinline__ void mma16816(float* c, const uint32_t* a, const uint32_t* b)
{
    asm volatile(
        "mma.sync.aligned.m16n8k16.row.col.f32.bf16.bf16.f32 "
        "{%0,%1,%2,%3}, {%4,%5,%6,%7}, {%8,%9}, {%0,%1,%2,%3};"
        : "+f"(c[0]), "+f"(c[1]), "+f"(c[2]), "+f"(c[3])
        : "r"(a[0]), "r"(a[1]), "r"(a[2]), "r"(a[3]), "r"(b[0]), "r"(b[1]));
}

// ---------------------------------------------------------------------------
// Tensor-core split-bf16 GEMM: Y = X @ W^T (+bias)
// X:[8192,1024] (hi,lo) bf16, W:[1024,1024] (hi,lo) bf16 (row = out-feature n).
// CTA tile 128x128, BK=32, 8 warps (2x4), warp tile 64x32.
// acc += Ah*Bh + Ah*Bl + Al*Bh  (split emulation, ~1.5e-5 rel err)
// ---------------------------------------------------------------------------
#define GM 128
#define GN 128
#define GK 32
#define KTOT 1024
// ASTR = smem row stride in bf16 units. 40 -> 80 bytes: multiple of 16 so
// uint4 tile-fill stores stay aligned (72B stride trapped: odd rows were
// 8-mod-16). Fragment loads: word index 20*qrow+qcol mod 32 covers all 32
// banks -> conflict-free.
#define ASTR 40

template<bool HEAD_LAYOUT, bool BIAS>
__global__ __launch_bounds__(256, 1)
void tc_gemm_kernel(const __nv_bfloat16* __restrict__ Ah, const __nv_bfloat16* __restrict__ Al,
                    const __nv_bfloat16* __restrict__ Bh, const __nv_bfloat16* __restrict__ Bl,
                    const float* __restrict__ bias, float* __restrict__ Y)
{
    __shared__ __nv_bfloat16 sAh[GM * ASTR];
    __shared__ __nv_bfloat16 sAl[GM * ASTR];
    __shared__ __nv_bfloat16 sBh[GN * ASTR];
    __shared__ __nv_bfloat16 sBl[GN * ASTR];

    const int tid = threadIdx.x;
    const int wid = tid >> 5, lane = tid & 31;
    const int warp_m = (wid >> 2) * 64;     // 0 or 64
    const int warp_n = (wid & 3) * 32;      // 0,32,64,96
    const int qrow = lane >> 2;             // 0..7
    const int qcol = lane & 3;              // 0..3
    const int m0 = blockIdx.y * GM;
    const int n0 = blockIdx.x * GN;

    float acc[4][4][4];
#pragma unroll
    for (int mi = 0; mi < 4; mi++)
#pragma unroll
        for (int ni = 0; ni < 4; ni++)
#pragma unroll
            for (int r = 0; r < 4; r++) acc[mi][ni][r] = 0.f;

    for (int k0 = 0; k0 < KTOT; k0 += GK) {
        __syncthreads();
        // Load tiles: 128 rows x 32 bf16 each. 512 groups of 8 bf16 (16B) per tile.
#pragma unroll
        for (int u = 0; u < 2; u++) {
            int g = tid + u * 256;          // 0..511
            int row = g >> 2, cb = g & 3;   // cb: 16B block (8 bf16)
            int so = row * ASTR + cb * 8;
            size_t ga = (size_t)(m0 + row) * KTOT + k0 + cb * 8;
            size_t gb = (size_t)(n0 + row) * KTOT + k0 + cb * 8;
            *(uint4*)&sAh[so] = *(const uint4*)(Ah + ga);
            *(uint4*)&sAl[so] = *(const uint4*)(Al + ga);
            *(uint4*)&sBh[so] = *(const uint4*)(Bh + gb);
            *(uint4*)&sBl[so] = *(const uint4*)(Bl + gb);
        }
        __syncthreads();

#pragma unroll
        for (int ks = 0; ks < 2; ks++) {
            const int kb = ks * 16;
            uint32_t afh[4][4], afl[4][4], bfh[4][2], bfl[4][2];
#pragma unroll
            for (int mi = 0; mi < 4; mi++) {
                int r0 = warp_m + mi * 16 + qrow;
                int c0 = kb + qcol * 2;
                afh[mi][0] = *(const uint32_t*)&sAh[r0 * ASTR + c0];
                afh[mi][1] = *(const uint32_t*)&sAh[(r0 + 8) * ASTR + c0];
                afh[mi][2] = *(const uint32_t*)&sAh[r0 * ASTR + c0 + 8];
                afh[mi][3] = *(const uint32_t*)&sAh[(r0 + 8) * ASTR + c0 + 8];
                afl[mi][0] = *(const uint32_t*)&sAl[r0 * ASTR + c0];
                afl[mi][1] = *(const uint32_t*)&sAl[(r0 + 8) * ASTR + c0];
                afl[mi][2] = *(const uint32_t*)&sAl[r0 * ASTR + c0 + 8];
                afl[mi][3] = *(const uint32_t*)&sAl[(r0 + 8) * ASTR + c0 + 8];
            }
#pragma unroll
            for (int ni = 0; ni < 4; ni++) {
                int nr = warp_n + ni * 8 + qrow;
                int c0 = kb + qcol * 2;
                bfh[ni][0] = *(const uint32_t*)&sBh[nr * ASTR + c0];
                bfh[ni][1] = *(const uint32_t*)&sBh[nr * ASTR + c0 + 8];
                bfl[ni][0] = *(const uint32_t*)&sBl[nr * ASTR + c0];
                bfl[ni][1] = *(const uint32_t*)&sBl[nr * ASTR + c0 + 8];
            }
#pragma unroll
            for (int mi = 0; mi < 4; mi++)
#pragma unroll
                for (int ni = 0; ni < 4; ni++) {
                    mma16816(acc[mi][ni], afh[mi], bfh[ni]);
                    mma16816(acc[mi][ni], afh[mi], bfl[ni]);
                    mma16816(acc[mi][ni], afl[mi], bfh[ni]);
                }
        }
    }

    // Epilogue: C fragment layout — lane holds (qrow, qcol*2..+1) and (+8, same)
#pragma unroll
    for (int mi = 0; mi < 4; mi++) {
#pragma unroll
        for (int ni = 0; ni < 4; ni++) {
            int m = m0 + warp_m + mi * 16 + qrow;
            int n = n0 + warp_n + ni * 8 + qcol * 2;
            float c0 = acc[mi][ni][0], c1 = acc[mi][ni][1];
            float c2 = acc[mi][ni][2], c3 = acc[mi][ni][3];
            if (BIAS) {
                float b0 = bias[n], b1 = bias[n + 1];
                c0 += b0; c1 += b1; c2 += b0; c3 += b1;
            }
            if (HEAD_LAYOUT) {
                int h = n >> 6, d = n & 63;
                {
                    int bb = m >> 11, t = m & (TZ - 1);
                    float* p = Y + (((size_t)(bb * HZ + h)) * TZ + t) * HDZ + d;
                    *(float2*)p = make_float2(c0, c1);
                }
                {
                    int m2 = m + 8;
                    int bb = m2 >> 11, t = m2 & (TZ - 1);
                    float* p = Y + (((size_t)(bb * HZ + h)) * TZ + t) * HDZ + d;
                    *(float2*)p = make_float2(c2, c3);
                }
            } else {
                *(float2*)(Y + (size_t)m * CZ + n)       = make_float2(c0, c1);
                *(float2*)(Y + (size_t)(m + 8) * CZ + n) = make_float2(c2, c3);
            }
        }
    }
}

// ---------------------------------------------------------------------------
// Flash attention (causal), fp32 — unchanged from R1
// ---------------------------------------------------------------------------
#define LDS 72
#define FLASH_SMEM ((4 * 64 * LDS + 3 * 64) * sizeof(float))

__global__ __launch_bounds__(256)
void flash_attn_kernel(float* __restrict__ ATT)
{
    extern __shared__ float sm[];
    float* Qt  = sm;
    float* Kt  = Qt + 64 * LDS;
    float* Vs  = Kt + 64 * LDS;
    float* St  = Vs + 64 * LDS;
    float* m_s = St + 64 * LDS;
    float* l_s = m_s + 64;
    float* al_s = l_s + 64;

    const int tid = threadIdx.x;
    const int tx = tid & 15, ty = tid >> 4;
    const int qt = blockIdx.x;
    const int bh = blockIdx.y;
    const int q0 = qt * 64;

    const int lrow = tid >> 2;
    const int dseg = (tid & 3) * 16;

    const float* Qg = g_qp + ((size_t)bh * TZ + q0) * HDZ;

#pragma unroll
    for (int u = 0; u < 4; u++) {
        float4 a = *(const float4*)(Qg + (size_t)lrow * HDZ + dseg + u * 4);
        Qt[(dseg + u * 4 + 0) * LDS + lrow] = a.x;
        Qt[(dseg + u * 4 + 1) * LDS + lrow] = a.y;
        Qt[(dseg + u * 4 + 2) * LDS + lrow] = a.z;
        Qt[(dseg + u * 4 + 3) * LDS + lrow] = a.w;
    }
    if (tid < 64) { m_s[tid] = -INFINITY; l_s[tid] = 0.f; }

    float o[4][4];
#pragma unroll
    for (int i = 0; i < 4; i++)
#pragma unroll
        for (int j = 0; j < 4; j++) o[i][j] = 0.f;

    for (int jt = 0; jt <= qt; jt++) {
        const int k0 = jt * 64;
        const float* Kg = g_kp + ((size_t)bh * TZ + k0) * HDZ;
        const float* Vg = g_vp + ((size_t)bh * TZ + k0) * HDZ;
        __syncthreads();
#pragma unroll
        for (int u = 0; u < 4; u++) {
            float4 kv = *(const float4*)(Kg + (size_t)lrow * HDZ + dseg + u * 4);
            Kt[(dseg + u * 4 + 0) * LDS + lrow] = kv.x;
            Kt[(dseg + u * 4 + 1) * LDS + lrow] = kv.y;
            Kt[(dseg + u * 4 + 2) * LDS + lrow] = kv.z;
            Kt[(dseg + u * 4 + 3) * LDS + lrow] = kv.w;
            float4 vv = *(const float4*)(Vg + (size_t)lrow * HDZ + dseg + u * 4);
            *(float4*)&Vs[lrow * LDS + dseg + u * 4] = vv;
        }
        __syncthreads();

        float s[4][4];
#pragma unroll
        for (int i = 0; i < 4; i++)
#pragma unroll
            for (int j = 0; j < 4; j++) s[i][j] = 0.f;
#pragma unroll
        for (int d = 0; d < 64; d++) {
            float4 av = *(const float4*)&Qt[d * LDS + ty * 4];
            float4 bv = *(const float4*)&Kt[d * LDS + tx * 4];
            float am[4] = {av.x, av.y, av.z, av.w};
            float bn[4] = {bv.x, bv.y, bv.z, bv.w};
#pragma unroll
            for (int i = 0; i < 4; i++)
#pragma unroll
                for (int j = 0; j < 4; j++) s[i][j] += am[i] * bn[j];
        }
        const bool diag = (jt == qt);
#pragma unroll
        for (int i = 0; i < 4; i++) {
            const int qi = ty * 4 + i;
#pragma unroll
            for (int j = 0; j < 4; j++) {
                float val = s[i][j] * ATT_SCALE;
                if (diag && (tx * 4 + j) > qi) val = -1e30f;
                St[(tx * 4 + j) * LDS + ty * 4 + i] = val;
            }
        }
        __syncthreads();

        {
            const int r = tid >> 2;
            const int cbase = (tid & 3) * 16;
            float mx = -1e30f;
#pragma unroll
            for (int c = 0; c < 16; c++)
                mx = fmaxf(mx, St[(cbase + c) * LDS + r]);
            mx = fmaxf(mx, __shfl_xor_sync(0xffffffff, mx, 1));
            mx = fmaxf(mx, __shfl_xor_sync(0xffffffff, mx, 2));
            const float m_old = m_s[r];
            const float m_new = fmaxf(m_old, mx);
            float sum = 0.f;
#pragma unroll
            for (int c = 0; c < 16; c++) {
                float p = __expf(St[(cbase + c) * LDS + r] - m_new);
                St[(cbase + c) * LDS + r] = p;
                sum += p;
            }
            sum += __shfl_xor_sync(0xffffffff, sum, 1);
            sum += __shfl_xor_sync(0xffffffff, sum, 2);
            if ((tid & 3) == 0) {
                const float al = __expf(m_old - m_new);
                al_s[r] = al;
                l_s[r] = l_s[r] * al + sum;
                m_s[r] = m_new;
            }
        }
        __syncthreads();

        float alr[4];
#pragma unroll
        for (int i = 0; i < 4; i++) alr[i] = al_s[ty * 4 + i];
#pragma unroll
        for (int i = 0; i < 4; i++)
#pragma unroll
            for (int j = 0; j < 4; j++) o[i][j] *= alr[i];
#pragma unroll
        for (int c = 0; c < 64; c++) {
            float4 pv = *(const float4*)&St[c * LDS + ty * 4];
            float4 vv = *(const float4*)&Vs[c * LDS + tx * 4];
            float pm[4] = {pv.x, pv.y, pv.z, pv.w};
            float vn[4] = {vv.x, vv.y, vv.z, vv.w};
#pragma unroll
            for (int i = 0; i < 4; i++)
#pragma unroll
                for (int j = 0; j < 4; j++) o[i][j] += pm[i] * vn[j];
        }
    }
    __syncthreads();

    const int b = bh / HZ;
    const int h = bh % HZ;
#pragma unroll
    for (int i = 0; i < 4; i++) {
        const float inv = 1.f / l_s[ty * 4 + i];
        const int t = q0 + ty * 4 + i;
        float* yp = ATT + ((size_t)(b * TZ + t)) * CZ + h * HDZ + tx * 4;
        float4 ov = make_float4(o[i][0] * inv, o[i][1] * inv, o[i][2] * inv, o[i][3] * inv);
        *(float4*)yp = ov;
    }
}

// ---------------------------------------------------------------------------
extern "C" void kernel_launch(void* const* d_in, const int* in_sizes, int n_in,
                              void* d_out, int out_size)
{
    const float* v  = (const float*)d_in[0];
    const float* k  = (const float*)d_in[1];
    const float* q  = (const float*)d_in[2];
    // d_in[3] = mask (exact causal tril; handled analytically)
    const float* Wk = (const float*)d_in[4];
    const float* Wq = (const float*)d_in[5];
    const float* Wv = (const float*)d_in[6];
    const float* Wo = (const float*)d_in[7];
    const float* bo = (const float*)d_in[8];
    float* out = (float*)d_out;

    float *qp, *kp, *vp, *att;
    __nv_bfloat16 *xh, *xl, *wh, *wl;
    cudaGetSymbolAddress((void**)&qp, g_qp);
    cudaGetSymbolAddress((void**)&kp, g_kp);
    cudaGetSymbolAddress((void**)&vp, g_vp);
    cudaGetSymbolAddress((void**)&att, g_att);
    cudaGetSymbolAddress((void**)&xh, g_xh);
    cudaGetSymbolAddress((void**)&xl, g_xl);
    cudaGetSymbolAddress((void**)&wh, g_wh);
    cudaGetSymbolAddress((void**)&wl, g_wl);

    cudaFuncSetAttribute(flash_attn_kernel,
                         cudaFuncAttributeMaxDynamicSharedMemorySize, FLASH_SMEM);

    const int NX = BZ * TZ * CZ;   // 8M
    const int NW = CZ * CZ;        // 1M
    dim3 gg(CZ / GN, (BZ * TZ) / GM);   // (8, 64)

    // Q projection
    split_kernel<<<NX / 1024, 256>>>(q, xh, xl, NX);
    split_kernel<<<NW / 1024, 256>>>(Wq, wh, wl, NW);
    tc_gemm_kernel<true, false><<<gg, 256>>>(xh, xl, wh, wl, nullptr, qp);
    // K projection
    split_kernel<<<NX / 1024, 256>>>(k, xh, xl, NX);
    split_kernel<<<NW / 1024, 256>>>(Wk, wh, wl, NW);
    tc_gemm_kernel<true, false><<<gg, 256>>>(xh, xl, wh, wl, nullptr, kp);
    // V projection
    split_kernel<<<NX / 1024, 256>>>(v, xh, xl, NX);
    split_kernel<<<NW / 1024, 256>>>(Wv, wh, wl, NW);
    tc_gemm_kernel<true, false><<<gg, 256>>>(xh, xl, wh, wl, nullptr, vp);

    // Attention
    dim3 fg(TZ / 64, BZ * HZ);
    flash_attn_kernel<<<fg, 256, FLASH_SMEM>>>(att);

    // Output projection (+bias)
    split_kernel<<<NX / 1024, 256>>>(att, xh, xl, NX);
    split_kernel<<<NW / 1024, 256>>>(Wo, wh, wl, NW);
    tc_gemm_kernel<false, true><<<gg, 256>>>(xh, xl, wh, wl, bo, out);
}

// round 12
// speedup vs baseline: 2.2183x; 1.4762x over previous
#include <cuda_runtime.h>
#include <cuda_bf16.h>
#include <math.h>
#include <stdint.h>

// Problem dims
#define BZ 4
#define TZ 2048
#define CZ 1024
#define HZ 16
#define HDZ 64
#define ATT_SCALE 0.5f   // 1/sqrt(B), faithful to reference

// ---------------------------------------------------------------------------
// Scratch (device globals; no allocation allowed)
// ---------------------------------------------------------------------------
__device__ __nv_bfloat16 g_qh[(size_t)BZ * HZ * TZ * HDZ]; // Q proj hi/lo [B,H,T,HD]
__device__ __nv_bfloat16 g_ql[(size_t)BZ * HZ * TZ * HDZ];
__device__ __nv_bfloat16 g_kh[(size_t)BZ * HZ * TZ * HDZ];
__device__ __nv_bfloat16 g_kl[(size_t)BZ * HZ * TZ * HDZ];
__device__ __nv_bfloat16 g_vh[(size_t)BZ * HZ * TZ * HDZ];
__device__ __nv_bfloat16 g_vl[(size_t)BZ * HZ * TZ * HDZ];
__device__ __nv_bfloat16 g_ath[(size_t)BZ * TZ * CZ];      // attention out hi/lo [B,T,C]
__device__ __nv_bfloat16 g_atl[(size_t)BZ * TZ * CZ];
__device__ __nv_bfloat16 g_xh[(size_t)BZ * TZ * CZ];       // split X
__device__ __nv_bfloat16 g_xl[(size_t)BZ * TZ * CZ];
__device__ __nv_bfloat16 g_wh[(size_t)CZ * CZ];            // split W
__device__ __nv_bfloat16 g_wl[(size_t)CZ * CZ];

// ---------------------------------------------------------------------------
// helpers
// ---------------------------------------------------------------------------
__device__ __forceinline__ uint32_t packbf(float a, float b) {
    __nv_bfloat16 ha = __float2bfloat16_rn(a);
    __nv_bfloat16 hb = __float2bfloat16_rn(b);
    uint16_t ua = *(uint16_t*)&ha, ub = *(uint16_t*)&hb;
    return (uint32_t)ua | ((uint32_t)ub << 16);   // low half = first k element
}
__device__ __forceinline__ void split1(float x, float& hi, float& lo) {
    __nv_bfloat16 h = __float2bfloat16_rn(x);
    hi = __bfloat162float(h);
    lo = x - hi;
}

// fp32 -> (hi, lo) bf16 split (bulk)
__global__ __launch_bounds__(256)
void split_kernel(const float* __restrict__ x, __nv_bfloat16* __restrict__ hi,
                  __nv_bfloat16* __restrict__ lo, int n)
{
    int i = (blockIdx.x * 256 + threadIdx.x) * 4;
    if (i >= n) return;
    float4 v = *(const float4*)(x + i);
    uint32_t h01 = packbf(v.x, v.y), h23 = packbf(v.z, v.w);
    float f0h = __bfloat162float(*(__nv_bfloat16*)&h01);
    uint32_t t1 = h01 >> 16; float f1h = __bfloat162float(*(__nv_bfloat16*)&t1);
    float f2h = __bfloat162float(*(__nv_bfloat16*)&h23);
    uint32_t t3 = h23 >> 16; float f3h = __bfloat162float(*(__nv_bfloat16*)&t3);
    uint32_t l01 = packbf(v.x - f0h, v.y - f1h), l23 = packbf(v.z - f2h, v.w - f3h);
    *(uint2*)(hi + i) = make_uint2(h01, h23);
    *(uint2*)(lo + i) = make_uint2(l01, l23);
}

// ---------------------------------------------------------------------------
// mma.sync m16n8k16 bf16 (fp32 accum)
// ---------------------------------------------------------------------------
__device__ __forceinline__ void mma16816(float* c, const uint32_t* a, const uint32_t* b)
{
    asm volatile(
        "mma.sync.aligned.m16n8k16.row.col.f32.bf16.bf16.f32 "
        "{%0,%1,%2,%3}, {%4,%5,%6,%7}, {%8,%9}, {%0,%1,%2,%3};"
        : "+f"(c[0]), "+f"(c[1]), "+f"(c[2]), "+f"(c[3])
        : "r"(a[0]), "r"(a[1]), "r"(a[2]), "r"(a[3]), "r"(b[0]), "r"(b[1]));
}

// ---------------------------------------------------------------------------
// Tensor-core split-bf16 GEMM: Y = X @ W^T (+bias)
// HEAD_LAYOUT: write bf16 hi/lo to Yh/Yl in [B,H,T,HD]; else fp32 Y [M,C] (+bias)
// ---------------------------------------------------------------------------
#define GM 128
#define GN 128
#define GK 32
#define KTOT 1024
#define ASTR 40   // 80B row stride: 16B-aligned uint4 stores; frag loads conflict-free

template<bool HEAD_LAYOUT, bool BIAS>
__global__ __launch_bounds__(256, 1)
void tc_gemm_kernel(const __nv_bfloat16* __restrict__ Ah, const __nv_bfloat16* __restrict__ Al,
                    const __nv_bfloat16* __restrict__ Bh, const __nv_bfloat16* __restrict__ Bl,
                    const float* __restrict__ bias, float* __restrict__ Y,
                    __nv_bfloat16* __restrict__ Yh, __nv_bfloat16* __restrict__ Yl)
{
    __shared__ __nv_bfloat16 sAh[GM * ASTR];
    __shared__ __nv_bfloat16 sAl[GM * ASTR];
    __shared__ __nv_bfloat16 sBh[GN * ASTR];
    __shared__ __nv_bfloat16 sBl[GN * ASTR];

    const int tid = threadIdx.x;
    const int wid = tid >> 5, lane = tid & 31;
    const int warp_m = (wid >> 2) * 64;
    const int warp_n = (wid & 3) * 32;
    const int qrow = lane >> 2;
    const int qcol = lane & 3;
    const int m0 = blockIdx.y * GM;
    const int n0 = blockIdx.x * GN;

    float acc[4][4][4];
#pragma unroll
    for (int mi = 0; mi < 4; mi++)
#pragma unroll
        for (int ni = 0; ni < 4; ni++)
#pragma unroll
            for (int r = 0; r < 4; r++) acc[mi][ni][r] = 0.f;

    for (int k0 = 0; k0 < KTOT; k0 += GK) {
        __syncthreads();
#pragma unroll
        for (int u = 0; u < 2; u++) {
            int g = tid + u * 256;
            int row = g >> 2, cb = g & 3;
            int so = row * ASTR + cb * 8;
            size_t ga = (size_t)(m0 + row) * KTOT + k0 + cb * 8;
            size_t gb = (size_t)(n0 + row) * KTOT + k0 + cb * 8;
            *(uint4*)&sAh[so] = *(const uint4*)(Ah + ga);
            *(uint4*)&sAl[so] = *(const uint4*)(Al + ga);
            *(uint4*)&sBh[so] = *(const uint4*)(Bh + gb);
            *(uint4*)&sBl[so] = *(const uint4*)(Bl + gb);
        }
        __syncthreads();

#pragma unroll
        for (int ks = 0; ks < 2; ks++) {
            const int kb = ks * 16;
            uint32_t afh[4][4], afl[4][4], bfh[4][2], bfl[4][2];
#pragma unroll
            for (int mi = 0; mi < 4; mi++) {
                int r0 = warp_m + mi * 16 + qrow;
                int c0 = kb + qcol * 2;
                afh[mi][0] = *(const uint32_t*)&sAh[r0 * ASTR + c0];
                afh[mi][1] = *(const uint32_t*)&sAh[(r0 + 8) * ASTR + c0];
                afh[mi][2] = *(const uint32_t*)&sAh[r0 * ASTR + c0 + 8];
                afh[mi][3] = *(const uint32_t*)&sAh[(r0 + 8) * ASTR + c0 + 8];
                afl[mi][0] = *(const uint32_t*)&sAl[r0 * ASTR + c0];
                afl[mi][1] = *(const uint32_t*)&sAl[(r0 + 8) * ASTR + c0];
                afl[mi][2] = *(const uint32_t*)&sAl[r0 * ASTR + c0 + 8];
                afl[mi][3] = *(const uint32_t*)&sAl[(r0 + 8) * ASTR + c0 + 8];
            }
#pragma unroll
            for (int ni = 0; ni < 4; ni++) {
                int nr = warp_n + ni * 8 + qrow;
                int c0 = kb + qcol * 2;
                bfh[ni][0] = *(const uint32_t*)&sBh[nr * ASTR + c0];
                bfh[ni][1] = *(const uint32_t*)&sBh[nr * ASTR + c0 + 8];
                bfl[ni][0] = *(const uint32_t*)&sBl[nr * ASTR + c0];
                bfl[ni][1] = *(const uint32_t*)&sBl[nr * ASTR + c0 + 8];
            }
#pragma unroll
            for (int mi = 0; mi < 4; mi++)
#pragma unroll
                for (int ni = 0; ni < 4; ni++) {
                    mma16816(acc[mi][ni], afh[mi], bfh[ni]);
                    mma16816(acc[mi][ni], afh[mi], bfl[ni]);
                    mma16816(acc[mi][ni], afl[mi], bfh[ni]);
                }
        }
    }

#pragma unroll
    for (int mi = 0; mi < 4; mi++) {
#pragma unroll
        for (int ni = 0; ni < 4; ni++) {
            int m = m0 + warp_m + mi * 16 + qrow;
            int n = n0 + warp_n + ni * 8 + qcol * 2;
            float c0 = acc[mi][ni][0], c1 = acc[mi][ni][1];
            float c2 = acc[mi][ni][2], c3 = acc[mi][ni][3];
            if (BIAS) {
                float b0 = bias[n], b1 = bias[n + 1];
                c0 += b0; c1 += b1; c2 += b0; c3 += b1;
            }
            if (HEAD_LAYOUT) {
                int h = n >> 6, d = n & 63;
                float h0, l0, h1, l1;
                {
                    int bb = m >> 11, t = m & (TZ - 1);
                    size_t idx = (((size_t)(bb * HZ + h)) * TZ + t) * HDZ + d;
                    split1(c0, h0, l0); split1(c1, h1, l1);
                    *(uint32_t*)(Yh + idx) = packbf(h0, h1);
                    *(uint32_t*)(Yl + idx) = packbf(l0, l1);
                }
                {
                    int m2 = m + 8;
                    int bb = m2 >> 11, t = m2 & (TZ - 1);
                    size_t idx = (((size_t)(bb * HZ + h)) * TZ + t) * HDZ + d;
                    split1(c2, h0, l0); split1(c3, h1, l1);
                    *(uint32_t*)(Yh + idx) = packbf(h0, h1);
                    *(uint32_t*)(Yl + idx) = packbf(l0, l1);
                }
            } else {
                *(float2*)(Y + (size_t)m * CZ + n)       = make_float2(c0, c1);
                *(float2*)(Y + (size_t)(m + 8) * CZ + n) = make_float2(c2, c3);
            }
        }
    }
}

// ---------------------------------------------------------------------------
// Tensor-core flash attention (causal), split-bf16 mma.sync.
// CTA: 128 q-rows x one (b,h). 8 warps, warp = 16 q-rows.
// KV tiles of 64. S and P*V via 3-product split; softmax in registers.
// ---------------------------------------------------------------------------
#define AQ 72   // Q/K smem stride (bf16): 144B rows, 16B-mult; frag banks distinct
#define AV 68   // V^T smem stride: 136B; ~2-way load conflicts
#define QN (128 * AQ)
#define KN (64 * AQ)
#define VN (64 * AV)
#define FLASH2_SMEM ((2 * QN + 2 * KN + 2 * VN) * (int)sizeof(__nv_bfloat16))

__global__ __launch_bounds__(256, 1)
void flash_tc_kernel(const __nv_bfloat16* __restrict__ Qh, const __nv_bfloat16* __restrict__ Ql,
                     const __nv_bfloat16* __restrict__ Kh, const __nv_bfloat16* __restrict__ Kl,
                     const __nv_bfloat16* __restrict__ Vh, const __nv_bfloat16* __restrict__ Vl,
                     __nv_bfloat16* __restrict__ Oh, __nv_bfloat16* __restrict__ Ol)
{
    extern __shared__ __nv_bfloat16 smb[];
    __nv_bfloat16* sQh = smb;
    __nv_bfloat16* sQl = sQh + QN;
    __nv_bfloat16* sKh = sQl + QN;
    __nv_bfloat16* sKl = sKh + KN;
    __nv_bfloat16* sVth = sKl + KN;
    __nv_bfloat16* sVtl = sVth + VN;

    const int tid = threadIdx.x;
    const int wid = tid >> 5, lane = tid & 31;
    const int qrow = lane >> 2, qcol = lane & 3;
    const int qt = blockIdx.x;
    const int bh = blockIdx.y;
    const int q0 = qt * 128;
    const size_t off = (size_t)bh * TZ * HDZ;

    // Fill Q (128 x 64, hi/lo)
    for (int i = tid; i < 128 * 8; i += 256) {
        int row = i >> 3, seg = i & 7;
        size_t ga = off + (size_t)(q0 + row) * HDZ + seg * 8;
        *(uint4*)&sQh[row * AQ + seg * 8] = *(const uint4*)(Qh + ga);
        *(uint4*)&sQl[row * AQ + seg * 8] = *(const uint4*)(Ql + ga);
    }

    float o[8][4];
#pragma unroll
    for (int nb = 0; nb < 8; nb++)
#pragma unroll
        for (int r = 0; r < 4; r++) o[nb][r] = 0.f;
    float m0r = -1e30f, m1r = -1e30f, l0 = 0.f, l1 = 0.f;

    uint32_t aQh[4][4], aQl[4][4];
    const int jmax = 2 * qt + 1;

    for (int jt = 0; jt <= jmax; jt++) {
        const int k0 = jt * 64;
        __syncthreads();
        // Fill K (64 x 64) and V^T (64d x 64kv)
        for (int i = tid; i < 64 * 8; i += 256) {
            int row = i >> 3, seg = i & 7;
            size_t ga = off + (size_t)(k0 + row) * HDZ + seg * 8;
            *(uint4*)&sKh[row * AQ + seg * 8] = *(const uint4*)(Kh + ga);
            *(uint4*)&sKl[row * AQ + seg * 8] = *(const uint4*)(Kl + ga);
            uint4 vh = *(const uint4*)(Vh + ga);
            uint4 vl = *(const uint4*)(Vl + ga);
            const __nv_bfloat16* ph = (const __nv_bfloat16*)&vh;
            const __nv_bfloat16* pl = (const __nv_bfloat16*)&vl;
#pragma unroll
            for (int j = 0; j < 8; j++) {
                sVth[(seg * 8 + j) * AV + row] = ph[j];
                sVtl[(seg * 8 + j) * AV + row] = pl[j];
            }
        }
        __syncthreads();

        if (jt == 0) {
#pragma unroll
            for (int kc = 0; kc < 4; kc++) {
                int r0 = wid * 16 + qrow;
                int c0 = kc * 16 + qcol * 2;
                aQh[kc][0] = *(const uint32_t*)&sQh[r0 * AQ + c0];
                aQh[kc][1] = *(const uint32_t*)&sQh[(r0 + 8) * AQ + c0];
                aQh[kc][2] = *(const uint32_t*)&sQh[r0 * AQ + c0 + 8];
                aQh[kc][3] = *(const uint32_t*)&sQh[(r0 + 8) * AQ + c0 + 8];
                aQl[kc][0] = *(const uint32_t*)&sQl[r0 * AQ + c0];
                aQl[kc][1] = *(const uint32_t*)&sQl[(r0 + 8) * AQ + c0];
                aQl[kc][2] = *(const uint32_t*)&sQl[r0 * AQ + c0 + 8];
                aQl[kc][3] = *(const uint32_t*)&sQl[(r0 + 8) * AQ + c0 + 8];
            }
        }

        // S = Q K^T (split, scaled)
        float s[8][4];
#pragma unroll
        for (int nb = 0; nb < 8; nb++)
#pragma unroll
            for (int r = 0; r < 4; r++) s[nb][r] = 0.f;
#pragma unroll
        for (int nb = 0; nb < 8; nb++) {
            int nr = nb * 8 + qrow;
#pragma unroll
            for (int kc = 0; kc < 4; kc++) {
                int c0 = kc * 16 + qcol * 2;
                uint32_t bh2[2] = {*(const uint32_t*)&sKh[nr * AQ + c0],
                                   *(const uint32_t*)&sKh[nr * AQ + c0 + 8]};
                uint32_t bl2[2] = {*(const uint32_t*)&sKl[nr * AQ + c0],
                                   *(const uint32_t*)&sKl[nr * AQ + c0 + 8]};
                mma16816(s[nb], aQh[kc], bh2);
                mma16816(s[nb], aQh[kc], bl2);
                mma16816(s[nb], aQl[kc], bh2);
            }
        }
#pragma unroll
        for (int nb = 0; nb < 8; nb++)
#pragma unroll
            for (int r = 0; r < 4; r++) s[nb][r] *= ATT_SCALE;

        // causal mask (only near-diagonal tiles)
        if (k0 + 63 > q0 + wid * 16) {
            int row0 = q0 + wid * 16 + qrow, row1 = row0 + 8;
#pragma unroll
            for (int nb = 0; nb < 8; nb++) {
                int col = k0 + nb * 8 + qcol * 2;
                if (col > row0)     s[nb][0] = -1e30f;
                if (col + 1 > row0) s[nb][1] = -1e30f;
                if (col > row1)     s[nb][2] = -1e30f;
                if (col + 1 > row1) s[nb][3] = -1e30f;
            }
        }

        // online softmax (register-resident; quad shfl for row stats)
        float mx0 = -1e30f, mx1 = -1e30f;
#pragma unroll
        for (int nb = 0; nb < 8; nb++) {
            mx0 = fmaxf(mx0, fmaxf(s[nb][0], s[nb][1]));
            mx1 = fmaxf(mx1, fmaxf(s[nb][2], s[nb][3]));
        }
        mx0 = fmaxf(mx0, __shfl_xor_sync(0xffffffffu, mx0, 1));
        mx0 = fmaxf(mx0, __shfl_xor_sync(0xffffffffu, mx0, 2));
        mx1 = fmaxf(mx1, __shfl_xor_sync(0xffffffffu, mx1, 1));
        mx1 = fmaxf(mx1, __shfl_xor_sync(0xffffffffu, mx1, 2));
        float mn0 = fmaxf(m0r, mx0), mn1 = fmaxf(m1r, mx1);
        float al0 = __expf(m0r - mn0), al1 = __expf(m1r - mn1);
        m0r = mn0; m1r = mn1;
        float sum0 = 0.f, sum1 = 0.f;
#pragma unroll
        for (int nb = 0; nb < 8; nb++) {
            s[nb][0] = __expf(s[nb][0] - mn0); sum0 += s[nb][0];
            s[nb][1] = __expf(s[nb][1] - mn0); sum0 += s[nb][1];
            s[nb][2] = __expf(s[nb][2] - mn1); sum1 += s[nb][2];
            s[nb][3] = __expf(s[nb][3] - mn1); sum1 += s[nb][3];
        }
        sum0 += __shfl_xor_sync(0xffffffffu, sum0, 1);
        sum0 += __shfl_xor_sync(0xffffffffu, sum0, 2);
        sum1 += __shfl_xor_sync(0xffffffffu, sum1, 1);
        sum1 += __shfl_xor_sync(0xffffffffu, sum1, 2);
        l0 = l0 * al0 + sum0;
        l1 = l1 * al1 + sum1;
#pragma unroll
        for (int nb = 0; nb < 8; nb++) {
            o[nb][0] *= al0; o[nb][1] *= al0;
            o[nb][2] *= al1; o[nb][3] *= al1;
        }

        // P fragments (hi/lo) directly from S C-fragments; O += P V (split)
        uint32_t aPh[4][4], aPl[4][4];
#pragma unroll
        for (int kvc = 0; kvc < 4; kvc++) {
            float h0, lo0, h1, lo1;
            split1(s[2 * kvc][0], h0, lo0); split1(s[2 * kvc][1], h1, lo1);
            aPh[kvc][0] = packbf(h0, h1);  aPl[kvc][0] = packbf(lo0, lo1);
            split1(s[2 * kvc][2], h0, lo0); split1(s[2 * kvc][3], h1, lo1);
            aPh[kvc][1] = packbf(h0, h1);  aPl[kvc][1] = packbf(lo0, lo1);
            split1(s[2 * kvc + 1][0], h0, lo0); split1(s[2 * kvc + 1][1], h1, lo1);
            aPh[kvc][2] = packbf(h0, h1);  aPl[kvc][2] = packbf(lo0, lo1);
            split1(s[2 * kvc + 1][2], h0, lo0); split1(s[2 * kvc + 1][3], h1, lo1);
            aPh[kvc][3] = packbf(h0, h1);  aPl[kvc][3] = packbf(lo0, lo1);
        }
#pragma unroll
        for (int nb = 0; nb < 8; nb++) {
            int nr = nb * 8 + qrow;
#pragma unroll
            for (int kvc = 0; kvc < 4; kvc++) {
                int c0 = kvc * 16 + qcol * 2;
                uint32_t bh2[2] = {*(const uint32_t*)&sVth[nr * AV + c0],
                                   *(const uint32_t*)&sVth[nr * AV + c0 + 8]};
                uint32_t bl2[2] = {*(const uint32_t*)&sVtl[nr * AV + c0],
                                   *(const uint32_t*)&sVtl[nr * AV + c0 + 8]};
                mma16816(o[nb], aPh[kvc], bh2);
                mma16816(o[nb], aPh[kvc], bl2);
                mma16816(o[nb], aPl[kvc], bh2);
            }
        }
    }

    // Normalize and write att (hi/lo bf16), layout [B,T,C] head-interleaved
    const float inv0 = 1.f / l0, inv1 = 1.f / l1;
    const int b = bh >> 4, h = bh & 15;
    const int row0 = q0 + wid * 16 + qrow, row1 = row0 + 8;
#pragma unroll
    for (int nb = 0; nb < 8; nb++) {
        int d = nb * 8 + qcol * 2;
        float h0, lo0, h1, lo1;
        {
            size_t idx = ((size_t)(b * TZ + row0)) * CZ + h * HDZ + d;
            split1(o[nb][0] * inv0, h0, lo0); split1(o[nb][1] * inv0, h1, lo1);
            *(uint32_t*)(Oh + idx) = packbf(h0, h1);
            *(uint32_t*)(Ol + idx) = packbf(lo0, lo1);
        }
        {
            size_t idx = ((size_t)(b * TZ + row1)) * CZ + h * HDZ + d;
            split1(o[nb][2] * inv1, h0, lo0); split1(o[nb][3] * inv1, h1, lo1);
            *(uint32_t*)(Oh + idx) = packbf(h0, h1);
            *(uint32_t*)(Ol + idx) = packbf(lo0, lo1);
        }
    }
}

// ---------------------------------------------------------------------------
extern "C" void kernel_launch(void* const* d_in, const int* in_sizes, int n_in,
                              void* d_out, int out_size)
{
    const float* v  = (const float*)d_in[0];
    const float* k  = (const float*)d_in[1];
    const float* q  = (const float*)d_in[2];
    // d_in[3] = mask (exact causal tril; handled analytically)
    const float* Wk = (const float*)d_in[4];
    const float* Wq = (const float*)d_in[5];
    const float* Wv = (const float*)d_in[6];
    const float* Wo = (const float*)d_in[7];
    const float* bo = (const float*)d_in[8];
    float* out = (float*)d_out;

    __nv_bfloat16 *qh, *ql, *kh, *kl, *vh, *vl, *ath, *atl, *xh, *xl, *wh, *wl;
    cudaGetSymbolAddress((void**)&qh, g_qh);
    cudaGetSymbolAddress((void**)&ql, g_ql);
    cudaGetSymbolAddress((void**)&kh, g_kh);
    cudaGetSymbolAddress((void**)&kl, g_kl);
    cudaGetSymbolAddress((void**)&vh, g_vh);
    cudaGetSymbolAddress((void**)&vl, g_vl);
    cudaGetSymbolAddress((void**)&ath, g_ath);
    cudaGetSymbolAddress((void**)&atl, g_atl);
    cudaGetSymbolAddress((void**)&xh, g_xh);
    cudaGetSymbolAddress((void**)&xl, g_xl);
    cudaGetSymbolAddress((void**)&wh, g_wh);
    cudaGetSymbolAddress((void**)&wl, g_wl);

    cudaFuncSetAttribute(flash_tc_kernel,
                         cudaFuncAttributeMaxDynamicSharedMemorySize, FLASH2_SMEM);

    const int NX = BZ * TZ * CZ;   // 8M
    const int NW = CZ * CZ;        // 1M
    dim3 gg(CZ / GN, (BZ * TZ) / GM);   // (8, 64)

    // Q projection
    split_kernel<<<NX / 1024, 256>>>(q, xh, xl, NX);
    split_kernel<<<NW / 1024, 256>>>(Wq, wh, wl, NW);
    tc_gemm_kernel<true, false><<<gg, 256>>>(xh, xl, wh, wl, nullptr, nullptr, qh, ql);
    // K projection
    split_kernel<<<NX / 1024, 256>>>(k, xh, xl, NX);
    split_kernel<<<NW / 1024, 256>>>(Wk, wh, wl, NW);
    tc_gemm_kernel<true, false><<<gg, 256>>>(xh, xl, wh, wl, nullptr, nullptr, kh, kl);
    // V projection
    split_kernel<<<NX / 1024, 256>>>(v, xh, xl, NX);
    split_kernel<<<NW / 1024, 256>>>(Wv, wh, wl, NW);
    tc_gemm_kernel<true, false><<<gg, 256>>>(xh, xl, wh, wl, nullptr, nullptr, vh, vl);

    // Attention (tensor-core flash)
    dim3 fg(TZ / 128, BZ * HZ);          // (16, 64)
    flash_tc_kernel<<<fg, 256, FLASH2_SMEM>>>(qh, ql, kh, kl, vh, vl, ath, atl);

    // Output projection (+bias) — reads att hi/lo directly
    split_kernel<<<NW / 1024, 256>>>(Wo, wh, wl, NW);
    tc_gemm_kernel<false, true><<<gg, 256>>>(ath, atl, wh, wl, bo, out, nullptr, nullptr);
}

// round 17
// speedup vs baseline: 2.4817x; 1.1187x over previous
#include <cuda_runtime.h>
#include <cuda_bf16.h>
#include <math.h>
#include <stdint.h>

// Problem dims
#define BZ 4
#define TZ 2048
#define CZ 1024
#define HZ 16
#define HDZ 64
#define ATT_SCALE 0.5f   // 1/sqrt(B), faithful to reference

// ---------------------------------------------------------------------------
// Scratch (device globals; no allocation allowed)
// ---------------------------------------------------------------------------
__device__ __nv_bfloat16 g_qh[(size_t)BZ * HZ * TZ * HDZ];
__device__ __nv_bfloat16 g_ql[(size_t)BZ * HZ * TZ * HDZ];
__device__ __nv_bfloat16 g_kh[(size_t)BZ * HZ * TZ * HDZ];
__device__ __nv_bfloat16 g_kl[(size_t)BZ * HZ * TZ * HDZ];
__device__ __nv_bfloat16 g_vh[(size_t)BZ * HZ * TZ * HDZ];
__device__ __nv_bfloat16 g_vl[(size_t)BZ * HZ * TZ * HDZ];
__device__ __nv_bfloat16 g_ath[(size_t)BZ * TZ * CZ];
__device__ __nv_bfloat16 g_atl[(size_t)BZ * TZ * CZ];
__device__ __nv_bfloat16 g_xh[(size_t)BZ * TZ * CZ];
__device__ __nv_bfloat16 g_xl[(size_t)BZ * TZ * CZ];
__device__ __nv_bfloat16 g_wh[(size_t)CZ * CZ];
__device__ __nv_bfloat16 g_wl[(size_t)CZ * CZ];

// ---------------------------------------------------------------------------
// helpers
// ---------------------------------------------------------------------------
__device__ __forceinline__ uint32_t packbf(float a, float b) {
    __nv_bfloat16 ha = __float2bfloat16_rn(a);
    __nv_bfloat16 hb = __float2bfloat16_rn(b);
    uint16_t ua = *(uint16_t*)&ha, ub = *(uint16_t*)&hb;
    return (uint32_t)ua | ((uint32_t)ub << 16);
}
__device__ __forceinline__ void split1(float x, float& hi, float& lo) {
    __nv_bfloat16 h = __float2bfloat16_rn(x);
    hi = __bfloat162float(h);
    lo = x - hi;
}
__device__ __forceinline__ uint32_t smem_cast(const void* p) {
    uint32_t a;
    asm("{ .reg .u64 t; cvta.to.shared.u64 t, %1; cvt.u32.u64 %0, t; }" : "=r"(a) : "l"(p));
    return a;
}
#define CP_ASYNC16(smaddr, gptr) \
    asm volatile("cp.async.cg.shared.global [%0], [%1], 16;" :: "r"(smaddr), "l"(gptr))
#define CP_COMMIT() asm volatile("cp.async.commit_group;" ::: "memory")
#define CP_WAIT1()  asm volatile("cp.async.wait_group 1;" ::: "memory")
#define CP_WAIT0()  asm volatile("cp.async.wait_group 0;" ::: "memory")

// fp32 -> (hi, lo) bf16 split (bulk)
__global__ __launch_bounds__(256)
void split_kernel(const float* __restrict__ x, __nv_bfloat16* __restrict__ hi,
                  __nv_bfloat16* __restrict__ lo, int n)
{
    int i = (blockIdx.x * 256 + threadIdx.x) * 4;
    if (i >= n) return;
    float4 v = *(const float4*)(x + i);
    uint32_t h01 = packbf(v.x, v.y), h23 = packbf(v.z, v.w);
    float f0h = __bfloat162float(*(__nv_bfloat16*)&h01);
    uint32_t t1 = h01 >> 16; float f1h = __bfloat162float(*(__nv_bfloat16*)&t1);
    float f2h = __bfloat162float(*(__nv_bfloat16*)&h23);
    uint32_t t3 = h23 >> 16; float f3h = __bfloat162float(*(__nv_bfloat16*)&t3);
    uint32_t l01 = packbf(v.x - f0h, v.y - f1h), l23 = packbf(v.z - f2h, v.w - f3h);
    *(uint2*)(hi + i) = make_uint2(h01, h23);
    *(uint2*)(lo + i) = make_uint2(l01, l23);
}

// ---------------------------------------------------------------------------
// mma.sync m16n8k16 bf16 (fp32 accum)
// ---------------------------------------------------------------------------
__device__ __forceinline__ void mma16816(float* c, const uint32_t* a, const uint32_t* b)
{
    asm volatile(
        "mma.sync.aligned.m16n8k16.row.col.f32.bf16.bf16.f32 "
        "{%0,%1,%2,%3}, {%4,%5,%6,%7}, {%8,%9}, {%0,%1,%2,%3};"
        : "+f"(c[0]), "+f"(c[1]), "+f"(c[2]), "+f"(c[3])
        : "r"(a[0]), "r"(a[1]), "r"(a[2]), "r"(a[3]), "r"(b[0]), "r"(b[1]));
}

// ---------------------------------------------------------------------------
// Tensor-core split-bf16 GEMM, cp.async double-buffered.
// ---------------------------------------------------------------------------
#define GM 128
#define GN 128
#define GK 32
#define KTOT 1024
#define NCHUNK (KTOT / GK)
#define ASTR 40            // 80B stride: 16B-aligned; frag loads conflict-free
#define TILE_E (GM * ASTR) // elements per tile (5120)
#define BUF_E (4 * TILE_E) // Ah,Al,Bh,Bl
#define GEMM_SMEM2 (2 * BUF_E * (int)sizeof(__nv_bfloat16))  // 81920 B

template<bool HEAD_LAYOUT, bool BIAS>
__global__ __launch_bounds__(256, 1)
void tc_gemm_kernel(const __nv_bfloat16* __restrict__ Ah, const __nv_bfloat16* __restrict__ Al,
                    const __nv_bfloat16* __restrict__ Bh, const __nv_bfloat16* __restrict__ Bl,
                    const float* __restrict__ bias, float* __restrict__ Y,
                    __nv_bfloat16* __restrict__ Yh, __nv_bfloat16* __restrict__ Yl)
{
    extern __shared__ __nv_bfloat16 smg[];

    const int tid = threadIdx.x;
    const int wid = tid >> 5, lane = tid & 31;
    const int warp_m = (wid >> 2) * 64;
    const int warp_n = (wid & 3) * 32;
    const int qrow = lane >> 2;
    const int qcol = lane & 3;
    const int m0 = blockIdx.y * GM;
    const int n0 = blockIdx.x * GN;

    // this thread's two fill slots (row, 16B-chunk) — same for every chunk
    const int g0row = tid >> 2,          g0cb = tid & 3;
    const int g1row = (tid + 256) >> 2,  g1cb = (tid + 256) & 3;
    const uint32_t so0 = (uint32_t)(g0row * ASTR + g0cb * 8) * 2;  // bytes
    const uint32_t so1 = (uint32_t)(g1row * ASTR + g1cb * 8) * 2;
    const uint32_t smbase = smem_cast(smg);

    auto issue = [&](int bsel, int k0) {
        const uint32_t sb = smbase + (uint32_t)bsel * BUF_E * 2;
        size_t ga0 = (size_t)(m0 + g0row) * KTOT + k0 + g0cb * 8;
        size_t gb0 = (size_t)(n0 + g0row) * KTOT + k0 + g0cb * 8;
        size_t ga1 = (size_t)(m0 + g1row) * KTOT + k0 + g1cb * 8;
        size_t gb1 = (size_t)(n0 + g1row) * KTOT + k0 + g1cb * 8;
        CP_ASYNC16(sb + so0,                Ah + ga0);
        CP_ASYNC16(sb + TILE_E * 2 + so0,   Al + ga0);
        CP_ASYNC16(sb + TILE_E * 4 + so0,   Bh + gb0);
        CP_ASYNC16(sb + TILE_E * 6 + so0,   Bl + gb0);
        CP_ASYNC16(sb + so1,                Ah + ga1);
        CP_ASYNC16(sb + TILE_E * 2 + so1,   Al + ga1);
        CP_ASYNC16(sb + TILE_E * 4 + so1,   Bh + gb1);
        CP_ASYNC16(sb + TILE_E * 6 + so1,   Bl + gb1);
    };

    float acc[4][4][4];
#pragma unroll
    for (int mi = 0; mi < 4; mi++)
#pragma unroll
        for (int ni = 0; ni < 4; ni++)
#pragma unroll
            for (int r = 0; r < 4; r++) acc[mi][ni][r] = 0.f;

    issue(0, 0);
    CP_COMMIT();

    for (int c = 0; c < NCHUNK; c++) {
        if (c + 1 < NCHUNK) {
            issue((c + 1) & 1, (c + 1) * GK);
            CP_COMMIT();
            CP_WAIT1();
        } else {
            CP_WAIT0();
        }
        __syncthreads();

        const __nv_bfloat16* sAh = smg + (size_t)(c & 1) * BUF_E;
        const __nv_bfloat16* sAl = sAh + TILE_E;
        const __nv_bfloat16* sBh = sAl + TILE_E;
        const __nv_bfloat16* sBl = sBh + TILE_E;

#pragma unroll
        for (int ks = 0; ks < 2; ks++) {
            const int kb = ks * 16;
            uint32_t afh[4][4], afl[4][4], bfh[4][2], bfl[4][2];
#pragma unroll
            for (int mi = 0; mi < 4; mi++) {
                int r0 = warp_m + mi * 16 + qrow;
                int c0 = kb + qcol * 2;
                afh[mi][0] = *(const uint32_t*)&sAh[r0 * ASTR + c0];
                afh[mi][1] = *(const uint32_t*)&sAh[(r0 + 8) * ASTR + c0];
                afh[mi][2] = *(const uint32_t*)&sAh[r0 * ASTR + c0 + 8];
                afh[mi][3] = *(const uint32_t*)&sAh[(r0 + 8) * ASTR + c0 + 8];
                afl[mi][0] = *(const uint32_t*)&sAl[r0 * ASTR + c0];
                afl[mi][1] = *(const uint32_t*)&sAl[(r0 + 8) * ASTR + c0];
                afl[mi][2] = *(const uint32_t*)&sAl[r0 * ASTR + c0 + 8];
                afl[mi][3] = *(const uint32_t*)&sAl[(r0 + 8) * ASTR + c0 + 8];
            }
#pragma unroll
            for (int ni = 0; ni < 4; ni++) {
                int nr = warp_n + ni * 8 + qrow;
                int c0 = kb + qcol * 2;
                bfh[ni][0] = *(const uint32_t*)&sBh[nr * ASTR + c0];
                bfh[ni][1] = *(const uint32_t*)&sBh[nr * ASTR + c0 + 8];
                bfl[ni][0] = *(const uint32_t*)&sBl[nr * ASTR + c0];
                bfl[ni][1] = *(const uint32_t*)&sBl[nr * ASTR + c0 + 8];
            }
#pragma unroll
            for (int mi = 0; mi < 4; mi++)
#pragma unroll
                for (int ni = 0; ni < 4; ni++) {
                    mma16816(acc[mi][ni], afh[mi], bfh[ni]);
                    mma16816(acc[mi][ni], afh[mi], bfl[ni]);
                    mma16816(acc[mi][ni], afl[mi], bfh[ni]);
                }
        }
        __syncthreads();
    }

#pragma unroll
    for (int mi = 0; mi < 4; mi++) {
#pragma unroll
        for (int ni = 0; ni < 4; ni++) {
            int m = m0 + warp_m + mi * 16 + qrow;
            int n = n0 + warp_n + ni * 8 + qcol * 2;
            float c0 = acc[mi][ni][0], c1 = acc[mi][ni][1];
            float c2 = acc[mi][ni][2], c3 = acc[mi][ni][3];
            if (BIAS) {
                float b0 = bias[n], b1 = bias[n + 1];
                c0 += b0; c1 += b1; c2 += b0; c3 += b1;
            }
            if (HEAD_LAYOUT) {
                int h = n >> 6, d = n & 63;
                float h0, l0, h1, l1;
                {
                    int bb = m >> 11, t = m & (TZ - 1);
                    size_t idx = (((size_t)(bb * HZ + h)) * TZ + t) * HDZ + d;
                    split1(c0, h0, l0); split1(c1, h1, l1);
                    *(uint32_t*)(Yh + idx) = packbf(h0, h1);
                    *(uint32_t*)(Yl + idx) = packbf(l0, l1);
                }
                {
                    int m2 = m + 8;
                    int bb = m2 >> 11, t = m2 & (TZ - 1);
                    size_t idx = (((size_t)(bb * HZ + h)) * TZ + t) * HDZ + d;
                    split1(c2, h0, l0); split1(c3, h1, l1);
                    *(uint32_t*)(Yh + idx) = packbf(h0, h1);
                    *(uint32_t*)(Yl + idx) = packbf(l0, l1);
                }
            } else {
                *(float2*)(Y + (size_t)m * CZ + n)       = make_float2(c0, c1);
                *(float2*)(Y + (size_t)(m + 8) * CZ + n) = make_float2(c2, c3);
            }
        }
    }
}

// ---------------------------------------------------------------------------
// Tensor-core flash attention (causal), split-bf16 mma.sync — unchanged (R12 WIN)
// ---------------------------------------------------------------------------
#define AQ 72
#define AV 68
#define QN (128 * AQ)
#define KN (64 * AQ)
#define VN (64 * AV)
#define FLASH2_SMEM ((2 * QN + 2 * KN + 2 * VN) * (int)sizeof(__nv_bfloat16))

__global__ __launch_bounds__(256, 1)
void flash_tc_kernel(const __nv_bfloat16* __restrict__ Qh, const __nv_bfloat16* __restrict__ Ql,
                     const __nv_bfloat16* __restrict__ Kh, const __nv_bfloat16* __restrict__ Kl,
                     const __nv_bfloat16* __restrict__ Vh, const __nv_bfloat16* __restrict__ Vl,
                     __nv_bfloat16* __restrict__ Oh, __nv_bfloat16* __restrict__ Ol)
{
    extern __shared__ __nv_bfloat16 smb[];
    __nv_bfloat16* sQh = smb;
    __nv_bfloat16* sQl = sQh + QN;
    __nv_bfloat16* sKh = sQl + QN;
    __nv_bfloat16* sKl = sKh + KN;
    __nv_bfloat16* sVth = sKl + KN;
    __nv_bfloat16* sVtl = sVth + VN;

    const int tid = threadIdx.x;
    const int wid = tid >> 5, lane = tid & 31;
    const int qrow = lane >> 2, qcol = lane & 3;
    const int qt = blockIdx.x;
    const int bh = blockIdx.y;
    const int q0 = qt * 128;
    const size_t off = (size_t)bh * TZ * HDZ;

    for (int i = tid; i < 128 * 8; i += 256) {
        int row = i >> 3, seg = i & 7;
        size_t ga = off + (size_t)(q0 + row) * HDZ + seg * 8;
        *(uint4*)&sQh[row * AQ + seg * 8] = *(const uint4*)(Qh + ga);
        *(uint4*)&sQl[row * AQ + seg * 8] = *(const uint4*)(Ql + ga);
    }

    float o[8][4];
#pragma unroll
    for (int nb = 0; nb < 8; nb++)
#pragma unroll
        for (int r = 0; r < 4; r++) o[nb][r] = 0.f;
    float m0r = -1e30f, m1r = -1e30f, l0 = 0.f, l1 = 0.f;

    uint32_t aQh[4][4], aQl[4][4];
    const int jmax = 2 * qt + 1;

    for (int jt = 0; jt <= jmax; jt++) {
        const int k0 = jt * 64;
        __syncthreads();
        for (int i = tid; i < 64 * 8; i += 256) {
            int row = i >> 3, seg = i & 7;
            size_t ga = off + (size_t)(k0 + row) * HDZ + seg * 8;
            *(uint4*)&sKh[row * AQ + seg * 8] = *(const uint4*)(Kh + ga);
            *(uint4*)&sKl[row * AQ + seg * 8] = *(const uint4*)(Kl + ga);
            uint4 vh = *(const uint4*)(Vh + ga);
            uint4 vl = *(const uint4*)(Vl + ga);
            const __nv_bfloat16* ph = (const __nv_bfloat16*)&vh;
            const __nv_bfloat16* pl = (const __nv_bfloat16*)&vl;
#pragma unroll
            for (int j = 0; j < 8; j++) {
                sVth[(seg * 8 + j) * AV + row] = ph[j];
                sVtl[(seg * 8 + j) * AV + row] = pl[j];
            }
        }
        __syncthreads();

        if (jt == 0) {
#pragma unroll
            for (int kc = 0; kc < 4; kc++) {
                int r0 = wid * 16 + qrow;
                int c0 = kc * 16 + qcol * 2;
                aQh[kc][0] = *(const uint32_t*)&sQh[r0 * AQ + c0];
                aQh[kc][1] = *(const uint32_t*)&sQh[(r0 + 8) * AQ + c0];
                aQh[kc][2] = *(const uint32_t*)&sQh[r0 * AQ + c0 + 8];
                aQh[kc][3] = *(const uint32_t*)&sQh[(r0 + 8) * AQ + c0 + 8];
                aQl[kc][0] = *(const uint32_t*)&sQl[r0 * AQ + c0];
                aQl[kc][1] = *(const uint32_t*)&sQl[(r0 + 8) * AQ + c0];
                aQl[kc][2] = *(const uint32_t*)&sQl[r0 * AQ + c0 + 8];
                aQl[kc][3] = *(const uint32_t*)&sQl[(r0 + 8) * AQ + c0 + 8];
            }
        }

        float s[8][4];
#pragma unroll
        for (int nb = 0; nb < 8; nb++)
#pragma unroll
            for (int r = 0; r < 4; r++) s[nb][r] = 0.f;
#pragma unroll
        for (int nb = 0; nb < 8; nb++) {
            int nr = nb * 8 + qrow;
#pragma unroll
            for (int kc = 0; kc < 4; kc++) {
                int c0 = kc * 16 + qcol * 2;
                uint32_t bh2[2] = {*(const uint32_t*)&sKh[nr * AQ + c0],
                                   *(const uint32_t*)&sKh[nr * AQ + c0 + 8]};
                uint32_t bl2[2] = {*(const uint32_t*)&sKl[nr * AQ + c0],
                                   *(const uint32_t*)&sKl[nr * AQ + c0 + 8]};
                mma16816(s[nb], aQh[kc], bh2);
                mma16816(s[nb], aQh[kc], bl2);
                mma16816(s[nb], aQl[kc], bh2);
            }
        }
#pragma unroll
        for (int nb = 0; nb < 8; nb++)
#pragma unroll
            for (int r = 0; r < 4; r++) s[nb][r] *= ATT_SCALE;

        if (k0 + 63 > q0 + wid * 16) {
            int row0 = q0 + wid * 16 + qrow, row1 = row0 + 8;
#pragma unroll
            for (int nb = 0; nb < 8; nb++) {
                int col = k0 + nb * 8 + qcol * 2;
                if (col > row0)     s[nb][0] = -1e30f;
                if (col + 1 > row0) s[nb][1] = -1e30f;
                if (col > row1)     s[nb][2] = -1e30f;
                if (col + 1 > row1) s[nb][3] = -1e30f;
            }
        }

        float mx0 = -1e30f, mx1 = -1e30f;
#pragma unroll
        for (int nb = 0; nb < 8; nb++) {
            mx0 = fmaxf(mx0, fmaxf(s[nb][0], s[nb][1]));
            mx1 = fmaxf(mx1, fmaxf(s[nb][2], s[nb][3]));
        }
        mx0 = fmaxf(mx0, __shfl_xor_sync(0xffffffffu, mx0, 1));
        mx0 = fmaxf(mx0, __shfl_xor_sync(0xffffffffu, mx0, 2));
        mx1 = fmaxf(mx1, __shfl_xor_sync(0xffffffffu, mx1, 1));
        mx1 = fmaxf(mx1, __shfl_xor_sync(0xffffffffu, mx1, 2));
        float mn0 = fmaxf(m0r, mx0), mn1 = fmaxf(m1r, mx1);
        float al0 = __expf(m0r - mn0), al1 = __expf(m1r - mn1);
        m0r = mn0; m1r = mn1;
        float sum0 = 0.f, sum1 = 0.f;
#pragma unroll
        for (int nb = 0; nb < 8; nb++) {
            s[nb][0] = __expf(s[nb][0] - mn0); sum0 += s[nb][0];
            s[nb][1] = __expf(s[nb][1] - mn0); sum0 += s[nb][1];
            s[nb][2] = __expf(s[nb][2] - mn1); sum1 += s[nb][2];
            s[nb][3] = __expf(s[nb][3] - mn1); sum1 += s[nb][3];
        }
        sum0 += __shfl_xor_sync(0xffffffffu, sum0, 1);
        sum0 += __shfl_xor_sync(0xffffffffu, sum0, 2);
        sum1 += __shfl_xor_sync(0xffffffffu, sum1, 1);
        sum1 += __shfl_xor_sync(0xffffffffu, sum1, 2);
        l0 = l0 * al0 + sum0;
        l1 = l1 * al1 + sum1;
#pragma unroll
        for (int nb = 0; nb < 8; nb++) {
            o[nb][0] *= al0; o[nb][1] *= al0;
            o[nb][2] *= al1; o[nb][3] *= al1;
        }

        uint32_t aPh[4][4], aPl[4][4];
#pragma unroll
        for (int kvc = 0; kvc < 4; kvc++) {
            float h0, lo0, h1, lo1;
            split1(s[2 * kvc][0], h0, lo0); split1(s[2 * kvc][1], h1, lo1);
            aPh[kvc][0] = packbf(h0, h1);  aPl[kvc][0] = packbf(lo0, lo1);
            split1(s[2 * kvc][2], h0, lo0); split1(s[2 * kvc][3], h1, lo1);
            aPh[kvc][1] = packbf(h0, h1);  aPl[kvc][1] = packbf(lo0, lo1);
            split1(s[2 * kvc + 1][0], h0, lo0); split1(s[2 * kvc + 1][1], h1, lo1);
            aPh[kvc][2] = packbf(h0, h1);  aPl[kvc][2] = packbf(lo0, lo1);
            split1(s[2 * kvc + 1][2], h0, lo0); split1(s[2 * kvc + 1][3], h1, lo1);
            aPh[kvc][3] = packbf(h0, h1);  aPl[kvc][3] = packbf(lo0, lo1);
        }
#pragma unroll
        for (int nb = 0; nb < 8; nb++) {
            int nr = nb * 8 + qrow;
#pragma unroll
            for (int kvc = 0; kvc < 4; kvc++) {
                int c0 = kvc * 16 + qcol * 2;
                uint32_t bh2[2] = {*(const uint32_t*)&sVth[nr * AV + c0],
                                   *(const uint32_t*)&sVth[nr * AV + c0 + 8]};
                uint32_t bl2[2] = {*(const uint32_t*)&sVtl[nr * AV + c0],
                                   *(const uint32_t*)&sVtl[nr * AV + c0 + 8]};
                mma16816(o[nb], aPh[kvc], bh2);
                mma16816(o[nb], aPh[kvc], bl2);
                mma16816(o[nb], aPl[kvc], bh2);
            }
        }
    }

    const float inv0 = 1.f / l0, inv1 = 1.f / l1;
    const int b = bh >> 4, h = bh & 15;
    const int row0 = q0 + wid * 16 + qrow, row1 = row0 + 8;
#pragma unroll
    for (int nb = 0; nb < 8; nb++) {
        int d = nb * 8 + qcol * 2;
        float h0, lo0, h1, lo1;
        {
            size_t idx = ((size_t)(b * TZ + row0)) * CZ + h * HDZ + d;
            split1(o[nb][0] * inv0, h0, lo0); split1(o[nb][1] * inv0, h1, lo1);
            *(uint32_t*)(Oh + idx) = packbf(h0, h1);
            *(uint32_t*)(Ol + idx) = packbf(lo0, lo1);
        }
        {
            size_t idx = ((size_t)(b * TZ + row1)) * CZ + h * HDZ + d;
            split1(o[nb][2] * inv1, h0, lo0); split1(o[nb][3] * inv1, h1, lo1);
            *(uint32_t*)(Oh + idx) = packbf(h0, h1);
            *(uint32_t*)(Ol + idx) = packbf(lo0, lo1);
        }
    }
}

// ---------------------------------------------------------------------------
extern "C" void kernel_launch(void* const* d_in, const int* in_sizes, int n_in,
                              void* d_out, int out_size)
{
    const float* v  = (const float*)d_in[0];
    const float* k  = (const float*)d_in[1];
    const float* q  = (const float*)d_in[2];
    const float* Wk = (const float*)d_in[4];
    const float* Wq = (const float*)d_in[5];
    const float* Wv = (const float*)d_in[6];
    const float* Wo = (const float*)d_in[7];
    const float* bo = (const float*)d_in[8];
    float* out = (float*)d_out;

    __nv_bfloat16 *qh, *ql, *kh, *kl, *vh, *vl, *ath, *atl, *xh, *xl, *wh, *wl;
    cudaGetSymbolAddress((void**)&qh, g_qh);
    cudaGetSymbolAddress((void**)&ql, g_ql);
    cudaGetSymbolAddress((void**)&kh, g_kh);
    cudaGetSymbolAddress((void**)&kl, g_kl);
    cudaGetSymbolAddress((void**)&vh, g_vh);
    cudaGetSymbolAddress((void**)&vl, g_vl);
    cudaGetSymbolAddress((void**)&ath, g_ath);
    cudaGetSymbolAddress((void**)&atl, g_atl);
    cudaGetSymbolAddress((void**)&xh, g_xh);
    cudaGetSymbolAddress((void**)&xl, g_xl);
    cudaGetSymbolAddress((void**)&wh, g_wh);
    cudaGetSymbolAddress((void**)&wl, g_wl);

    cudaFuncSetAttribute(flash_tc_kernel,
                         cudaFuncAttributeMaxDynamicSharedMemorySize, FLASH2_SMEM);
    cudaFuncSetAttribute(tc_gemm_kernel<true, false>,
                         cudaFuncAttributeMaxDynamicSharedMemorySize, GEMM_SMEM2);
    cudaFuncSetAttribute(tc_gemm_kernel<false, true>,
                         cudaFuncAttributeMaxDynamicSharedMemorySize, GEMM_SMEM2);

    const int NX = BZ * TZ * CZ;
    const int NW = CZ * CZ;
    dim3 gg(CZ / GN, (BZ * TZ) / GM);   // (8, 64)

    split_kernel<<<NX / 1024, 256>>>(q, xh, xl, NX);
    split_kernel<<<NW / 1024, 256>>>(Wq, wh, wl, NW);
    tc_gemm_kernel<true, false><<<gg, 256, GEMM_SMEM2>>>(xh, xl, wh, wl, nullptr, nullptr, qh, ql);
    split_kernel<<<NX / 1024, 256>>>(k, xh, xl, NX);
    split_kernel<<<NW / 1024, 256>>>(Wk, wh, wl, NW);
    tc_gemm_kernel<true, false><<<gg, 256, GEMM_SMEM2>>>(xh, xl, wh, wl, nullptr, nullptr, kh, kl);
    split_kernel<<<NX / 1024, 256>>>(v, xh, xl, NX);
    split_kernel<<<NW / 1024, 256>>>(Wv, wh, wl, NW);
    tc_gemm_kernel<true, false><<<gg, 256, GEMM_SMEM2>>>(xh, xl, wh, wl, nullptr, nullptr, vh, vl);

    dim3 fg(TZ / 128, BZ * HZ);
    flash_tc_kernel<<<fg, 256, FLASH2_SMEM>>>(qh, ql, kh, kl, vh, vl, ath, atl);

    split_kernel<<<NW / 1024, 256>>>(Wo, wh, wl, NW);
    tc_gemm_kernel<false, true><<<gg, 256, GEMM_SMEM2>>>(ath, atl, wh, wl, bo, out, nullptr, nullptr);
}